// round 10
// baseline (speedup 1.0000x reference)
#include <cuda_runtime.h>
#include <cuda_bf16.h>
#include <cstdint>

#define NTOK 4096
#define HID  1024
#define NEXP 64
#define TOPK 8
#define IDIM 768
#define FLAT (NTOK*TOPK)
#define BM   128
#define MPAD 40960
#define MAXTILES 320

// ---------------- scratch ----------------
static __device__ float g_inter[(size_t)MPAD * IDIM];
static __device__ float g_y2[(size_t)MPAD * HID];
static __device__ float g_topkw[FLAT];
static __device__ int   g_flatexp[FLAT];
static __device__ int   g_invperm[FLAT];
static __device__ int   g_rowtok[MPAD];
static __device__ int   g_counts[NEXP];
static __device__ int   g_ctr[NEXP];
static __device__ int   g_offpad[NEXP];
static __device__ int   g_tile_e[MAXTILES];
static __device__ int   g_tile_r0[MAXTILES];
static __device__ int   g_ntiles;

// ---------------- helpers ----------------
__device__ __forceinline__ uint32_t smem_u32(const void* p) {
    uint32_t a;
    asm("{ .reg .u64 t; cvta.to.shared.u64 t, %1; cvt.u32.u64 %0, t; }" : "=r"(a) : "l"(p));
    return a;
}
#define STS128(a, v) \
    asm volatile("st.shared.v4.b32 [%0], {%1, %2, %3, %4};" \
        :: "r"(a), "r"((v).x), "r"((v).y), "r"((v).z), "r"((v).w) : "memory")

__device__ __forceinline__ void ldsm_x4(uint32_t (&r)[4], uint32_t addr) {
    asm volatile("ldmatrix.sync.aligned.m8n8.x4.shared.b16 {%0,%1,%2,%3}, [%4];"
        : "=r"(r[0]), "=r"(r[1]), "=r"(r[2]), "=r"(r[3]) : "r"(addr));
}
__device__ __forceinline__ void mma16816(float (&d)[4], const uint32_t (&a)[4], const uint32_t (&b)[2]) {
    asm volatile("mma.sync.aligned.m16n8k16.row.col.f32.bf16.bf16.f32 "
        "{%0,%1,%2,%3}, {%4,%5,%6,%7}, {%8,%9}, {%0,%1,%2,%3};"
        : "+f"(d[0]), "+f"(d[1]), "+f"(d[2]), "+f"(d[3])
        : "r"(a[0]), "r"(a[1]), "r"(a[2]), "r"(a[3]), "r"(b[0]), "r"(b[1]));
}

// fp32x8 -> bf16 hi/lo split
__device__ __forceinline__ void cvt8(const float4 f0, const float4 f1, uint4& H, uint4& L) {
    __nv_bfloat162 h;
    h = __float22bfloat162_rn(make_float2(f0.x, f0.y)); uint32_t u0 = *(uint32_t*)&h;
    h = __float22bfloat162_rn(make_float2(f0.z, f0.w)); uint32_t u1 = *(uint32_t*)&h;
    h = __float22bfloat162_rn(make_float2(f1.x, f1.y)); uint32_t u2 = *(uint32_t*)&h;
    h = __float22bfloat162_rn(make_float2(f1.z, f1.w)); uint32_t u3 = *(uint32_t*)&h;
    H = make_uint4(u0, u1, u2, u3);
    float l0 = f0.x - __uint_as_float(u0 << 16);
    float l1 = f0.y - __uint_as_float(u0 & 0xFFFF0000u);
    float l2 = f0.z - __uint_as_float(u1 << 16);
    float l3 = f0.w - __uint_as_float(u1 & 0xFFFF0000u);
    float l4 = f1.x - __uint_as_float(u2 << 16);
    float l5 = f1.y - __uint_as_float(u2 & 0xFFFF0000u);
    float l6 = f1.z - __uint_as_float(u3 << 16);
    float l7 = f1.w - __uint_as_float(u3 & 0xFFFF0000u);
    h = __float22bfloat162_rn(make_float2(l0, l1)); uint32_t v0 = *(uint32_t*)&h;
    h = __float22bfloat162_rn(make_float2(l2, l3)); uint32_t v1 = *(uint32_t*)&h;
    h = __float22bfloat162_rn(make_float2(l4, l5)); uint32_t v2 = *(uint32_t*)&h;
    h = __float22bfloat162_rn(make_float2(l6, l7)); uint32_t v3 = *(uint32_t*)&h;
    L = make_uint4(v0, v1, v2, v3);
}

// swizzled byte offset within a [rows][16 bf16] tile (32B rows, 2x16B chunks)
__device__ __forceinline__ uint32_t swz16(int row, int ch) {
    return (uint32_t)(row * 32 + ((ch ^ ((row >> 2) & 1)) << 4));
}

// ---------------- small kernels (gemm1 stays the 4th launch for ncu) ----------------
__global__ void initfill_kernel() {
    int i = blockIdx.x * 256 + threadIdx.x;
    if (i < MPAD) g_rowtok[i] = -1;
    if (i < NEXP) { g_counts[i] = 0; g_ctr[i] = 0; }
}

#define RT 8
__global__ void router_kernel(const float* __restrict__ x, const float* __restrict__ gate) {
    __shared__ float xs[RT][HID];
    __shared__ float lg[RT][NEXP];
    int t0 = blockIdx.x * RT;
    int tid = threadIdx.x;  // 256
    const float4* xsrc = (const float4*)(x + (size_t)t0 * HID);
    for (int i = tid; i < RT * HID / 4; i += 256) ((float4*)&xs[0][0])[i] = xsrc[i];
    __syncthreads();
    int tt = tid >> 5, lane = tid & 31;
    #pragma unroll
    for (int g = 0; g < 2; g++) {
        int e = g * 32 + lane;
        const float* gp = gate + (size_t)e * HID;
        float s = 0.f;
        #pragma unroll 4
        for (int k = 0; k < HID; k += 4) {
            float4 gv = *(const float4*)(gp + k);
            s += xs[tt][k] * gv.x + xs[tt][k+1] * gv.y + xs[tt][k+2] * gv.z + xs[tt][k+3] * gv.w;
        }
        lg[tt][e] = s;
    }
    __syncthreads();
    if (tid < RT) {
        int t = t0 + tid;
        float mx = lg[tid][0];
        #pragma unroll
        for (int e = 1; e < NEXP; e++) mx = fmaxf(mx, lg[tid][e]);
        unsigned long long taken = 0ull;
        float wsum = 0.f;
        int sel[TOPK]; float wv[TOPK];
        for (int k = 0; k < TOPK; k++) {
            int best = 0; float bv = -1e30f;
            for (int e = 0; e < NEXP; e++) {
                float v = lg[tid][e];
                if (!((taken >> e) & 1ull) && v > bv) { bv = v; best = e; }
            }
            taken |= 1ull << best;
            sel[k] = best;
            float w = expf(lg[tid][best] - mx);
            wv[k] = w; wsum += w;
            atomicAdd(&g_counts[best], 1);
        }
        float inv = 1.f / wsum;
        for (int k = 0; k < TOPK; k++) {
            g_topkw[t * TOPK + k]   = wv[k] * inv;
            g_flatexp[t * TOPK + k] = sel[k];
        }
    }
}

__global__ void metascatter_kernel() {
    int tid = threadIdx.x;   // 256
    if (tid == 0) {
        int nt = 0, cum = 0;
        for (int e = 0; e < NEXP; e++) {
            g_offpad[e] = cum;
            int c = g_counts[e];
            int t = (c + BM - 1) / BM;
            for (int j = 0; j < t; j++) { g_tile_e[nt] = e; g_tile_r0[nt] = cum + j * BM; nt++; }
            cum += t * BM;
        }
        g_ntiles = nt;
    }
    __syncthreads();
    for (int i = tid; i < FLAT; i += 256) {
        int e = g_flatexp[i];
        int dest = g_offpad[e] + atomicAdd(&g_ctr[e], 1);
        g_rowtok[dest] = i >> 3;
        g_invperm[i] = dest;
    }
}

// ---------------- grouped GEMM: CTA 128x256, warp tile 64x64, KC=16 double-buffer ----
// 8 warps (wm=wid>>2 in 0..1, wn=wid&3 in 0..3). acc[4][8][4] = 128 fp32 regs.
// Buffer = Ahi(4K)|Alo(4K)|Bhi(8K)|Blo(8K) = 24KB; 2 buffers = 48KB of 64KB dynamic smem.
// FUSED (GEMM1): B rows 0-127 = gate[nb*128+r], 128-255 = up[nb*128+(r-128)];
//                epilogue silu(g)*u via 64KB smem exchange -> g_inter (128 cols/CTA).
// else  (GEMM2): B rows = down[nb*256+r]; epilogue -> g_y2.

#define BUF_SZ  24576
#define OFF_ALO 4096
#define OFF_BHI 8192
#define OFF_BLO 16384
#define SMEM_BYTES 65536

template<bool FUSED>
__global__ void __launch_bounds__(256, 1) moe_gemm(const float* __restrict__ Ain,
                                                   const float* __restrict__ W) {
    constexpr int KDIM = FUSED ? HID : IDIM;   // 1024 / 768
    constexpr int NK   = KDIM / 16;            // 64 / 48
    int tile = blockIdx.x;
    if (tile >= g_ntiles) return;
    int e = g_tile_e[tile], row0 = g_tile_r0[tile], nb = blockIdx.y;

    extern __shared__ __align__(128) char smem[];
    uint32_t sb = smem_u32(smem);

    int tid = threadIdx.x, lane = tid & 31, wid = tid >> 5;
    int wm = wid >> 2, wn = wid & 3;

    // -------- copy mapping: A row = tid/2 (0..127); B rows = tid/2 and tid/2+128; ch = tid&1
    int rA = tid >> 1, chA = tid & 1;
    uint32_t soffA  = swz16(rA, chA);
    uint32_t soffB0 = swz16(rA, chA);
    uint32_t soffB1 = swz16(rA + 128, chA);

    const float* A = FUSED ? Ain : (const float*)g_inter;
    const float* aptr;
    if (FUSED) {
        int t0 = g_rowtok[row0 + rA];
        aptr = (t0 >= 0) ? A + (size_t)t0 * HID + chA * 8 : nullptr;
    } else {
        aptr = A + (size_t)(row0 + rA) * IDIM + chA * 8;
    }
    const float* Wb = W + (size_t)e * (size_t)(FUSED ? 2 * IDIM : HID) * KDIM;
    int wr0 = FUSED ? (nb * 128 + rA) : (nb * 256 + rA);
    int wr1 = FUSED ? (IDIM + nb * 128 + rA) : (nb * 256 + rA + 128);
    const float* bptr0 = Wb + (size_t)wr0 * KDIM + chA * 8;
    const float* bptr1 = Wb + (size_t)wr1 * KDIM + chA * 8;

    float acc[4][8][4];
    #pragma unroll
    for (int a = 0; a < 4; a++)
        #pragma unroll
        for (int b = 0; b < 8; b++)
            #pragma unroll
            for (int c = 0; c < 4; c++) acc[a][b][c] = 0.f;

    const float4 Z = make_float4(0.f, 0.f, 0.f, 0.f);
    float4 pa0, pa1, pb0, pb1, pb2, pb3;
    // prefetch kt = 0
    pa0 = aptr ? *(const float4*)(aptr)     : Z;
    pa1 = aptr ? *(const float4*)(aptr + 4) : Z;
    pb0 = *(const float4*)(bptr0);  pb1 = *(const float4*)(bptr0 + 4);
    pb2 = *(const float4*)(bptr1);  pb3 = *(const float4*)(bptr1 + 4);
    // fill buffer 0
    {
        uint4 H, L;
        cvt8(pa0, pa1, H, L); STS128(sb + soffA, H);            STS128(sb + OFF_ALO + soffA, L);
        cvt8(pb0, pb1, H, L); STS128(sb + OFF_BHI + soffB0, H); STS128(sb + OFF_BLO + soffB0, L);
        cvt8(pb2, pb3, H, L); STS128(sb + OFF_BHI + soffB1, H); STS128(sb + OFF_BLO + soffB1, L);
    }
    __syncthreads();

    #pragma unroll 1
    for (int kt = 0; kt < NK; kt++) {
        uint32_t cur = sb + (uint32_t)((kt & 1) * BUF_SZ);
        // issue next-tile LDGs early
        if (kt + 1 < NK) {
            int ko = (kt + 1) * 16;
            pa0 = aptr ? *(const float4*)(aptr + ko)     : Z;
            pa1 = aptr ? *(const float4*)(aptr + ko + 4) : Z;
            pb0 = *(const float4*)(bptr0 + ko);  pb1 = *(const float4*)(bptr0 + ko + 4);
            pb2 = *(const float4*)(bptr1 + ko);  pb3 = *(const float4*)(bptr1 + ko + 4);
        }

        // -------- compute one k=16 slab (warp tile 64x64)
        {
            uint32_t aH[4][4], aL[4][4];
            #pragma unroll
            for (int mt = 0; mt < 4; mt++) {
                int row = wm * 64 + mt * 16 + (lane & 15);
                uint32_t ad = swz16(row, lane >> 4);
                ldsm_x4(aH[mt], cur + ad);
                ldsm_x4(aL[mt], cur + OFF_ALO + ad);
            }
            #pragma unroll
            for (int np = 0; np < 4; np++) {
                int row = wn * 64 + np * 16 + (lane & 7) + ((lane >> 4) << 3);
                uint32_t bd = swz16(row, (lane >> 3) & 1);
                uint32_t tH[4], tL[4];
                ldsm_x4(tH, cur + OFF_BHI + bd);
                ldsm_x4(tL, cur + OFF_BLO + bd);
                uint32_t bH0[2] = {tH[0], tH[1]}, bH1[2] = {tH[2], tH[3]};
                uint32_t bL0[2] = {tL[0], tL[1]}, bL1[2] = {tL[2], tL[3]};
                #pragma unroll
                for (int mt = 0; mt < 4; mt++) {
                    mma16816(acc[mt][2*np],   aH[mt], bH0);
                    mma16816(acc[mt][2*np],   aH[mt], bL0);
                    mma16816(acc[mt][2*np],   aL[mt], bH0);
                    mma16816(acc[mt][2*np+1], aH[mt], bH1);
                    mma16816(acc[mt][2*np+1], aH[mt], bL1);
                    mma16816(acc[mt][2*np+1], aL[mt], bH1);
                }
            }
        }

        // stage next slab into the other buffer
        if (kt + 1 < NK) {
            uint32_t nxt = sb + (uint32_t)(((kt + 1) & 1) * BUF_SZ);
            uint4 H, L;
            cvt8(pa0, pa1, H, L); STS128(nxt + soffA, H);            STS128(nxt + OFF_ALO + soffA, L);
            cvt8(pb0, pb1, H, L); STS128(nxt + OFF_BHI + soffB0, H); STS128(nxt + OFF_BLO + soffB0, L);
            cvt8(pb2, pb3, H, L); STS128(nxt + OFF_BHI + soffB1, H); STS128(nxt + OFF_BLO + soffB1, L);
        }
        __syncthreads();
    }

    if (FUSED) {
        float* sUp = (float*)smem;   // [128][128] f32 = 64KB
        if (wn >= 2) {               // up warps: cols 128..255
            #pragma unroll
            for (int mt = 0; mt < 4; mt++)
                #pragma unroll
                for (int nt = 0; nt < 8; nt++) {
                    int m = wm * 64 + mt * 16 + (lane >> 2);
                    int c = (wn - 2) * 64 + nt * 8 + (lane & 3) * 2;
                    sUp[m * 128 + c]           = acc[mt][nt][0];
                    sUp[m * 128 + c + 1]       = acc[mt][nt][1];
                    sUp[(m + 8) * 128 + c]     = acc[mt][nt][2];
                    sUp[(m + 8) * 128 + c + 1] = acc[mt][nt][3];
                }
        }
        __syncthreads();
        if (wn < 2) {                // gate warps: cols 0..127
            #pragma unroll
            for (int mt = 0; mt < 4; mt++)
                #pragma unroll
                for (int nt = 0; nt < 8; nt++) {
                    int m = wm * 64 + mt * 16 + (lane >> 2);
                    int c = wn * 64 + nt * 8 + (lane & 3) * 2;
                    #pragma unroll
                    for (int h = 0; h < 2; h++) {
                        int mm = m + h * 8;
                        float g0 = acc[mt][nt][h * 2], g1 = acc[mt][nt][h * 2 + 1];
                        float u0 = sUp[mm * 128 + c], u1 = sUp[mm * 128 + c + 1];
                        float2 o;
                        o.x = g0 / (1.f + expf(-g0)) * u0;
                        o.y = g1 / (1.f + expf(-g1)) * u1;
                        *(float2*)&g_inter[(size_t)(row0 + mm) * IDIM + nb * 128 + c] = o;
                    }
                }
        }
    } else {
        #pragma unroll
        for (int mt = 0; mt < 4; mt++)
            #pragma unroll
            for (int nt = 0; nt < 8; nt++) {
                int m = row0 + wm * 64 + mt * 16 + (lane >> 2);
                int c = nb * 256 + wn * 64 + nt * 8 + (lane & 3) * 2;
                *(float2*)&g_y2[(size_t)m * HID + c]       = make_float2(acc[mt][nt][0], acc[mt][nt][1]);
                *(float2*)&g_y2[(size_t)(m + 8) * HID + c] = make_float2(acc[mt][nt][2], acc[mt][nt][3]);
            }
    }
}

// ---------------- combine ----------------
__global__ void combine_kernel(float* __restrict__ out) {
    __shared__ float w[TOPK];
    __shared__ int rows[TOPK];
    int t = blockIdx.x;
    int tid = threadIdx.x;
    if (tid < TOPK) {
        w[tid]    = g_topkw[t * TOPK + tid];
        rows[tid] = g_invperm[t * TOPK + tid];
    }
    __syncthreads();
    float4 acc = make_float4(0.f, 0.f, 0.f, 0.f);
    #pragma unroll
    for (int k = 0; k < TOPK; k++) {
        const float4 v = *(const float4*)&g_y2[(size_t)rows[k] * HID + (tid << 2)];
        float wk = w[k];
        acc.x += wk * v.x; acc.y += wk * v.y; acc.z += wk * v.z; acc.w += wk * v.w;
    }
    *(float4*)(out + (size_t)t * HID + (tid << 2)) = acc;
}

// ---------------- launch ----------------
extern "C" void kernel_launch(void* const* d_in, const int* in_sizes, int n_in,
                              void* d_out, int out_size) {
    const float* x    = (const float*)d_in[0];
    const float* gate = (const float*)d_in[1];
    const float* gup  = (const float*)d_in[2];
    const float* dwn  = (const float*)d_in[3];
    float* out = (float*)d_out;

    cudaFuncSetAttribute(moe_gemm<true>,  cudaFuncAttributeMaxDynamicSharedMemorySize, SMEM_BYTES);
    cudaFuncSetAttribute(moe_gemm<false>, cudaFuncAttributeMaxDynamicSharedMemorySize, SMEM_BYTES);

    initfill_kernel<<<(MPAD + 255) / 256, 256>>>();                     // launch 0
    router_kernel<<<NTOK / RT, 256>>>(x, gate);                         // launch 1
    metascatter_kernel<<<1, 256>>>();                                   // launch 2
    moe_gemm<true><<<dim3(MAXTILES, IDIM / 128), 256, SMEM_BYTES>>>(x, gup);       // launch 3 (profiled)
    moe_gemm<false><<<dim3(MAXTILES, HID / 256), 256, SMEM_BYTES>>>(nullptr, dwn); // launch 4
    combine_kernel<<<NTOK, 256>>>(out);                                 // launch 5
}